// round 8
// baseline (speedup 1.0000x reference)
#include <cuda_runtime.h>
#include <cstdint>
#include <algorithm>

// Problem constants (fixed by dataset shapes)
#define BATCH 4
#define NV    4096
#define NC    128
#define NS    1024   // NV / POOLING_RATE
#define KNBR  4
#define PLF   (NV * 3)        // floats per (b,c) feature plane = 12288
#define PLB   (PLF * 4)       // bytes per plane = 49152
#define VBB   (NV * 3 * 4)    // bytes per batch of vertices = 49152
#define CAND  64              // phase-2 candidate buffer depth per query

typedef unsigned long long ull;

struct Samp { int s[NS]; };   // 4KB by-value kernel parameter

// -------- device scratch (no allocation allowed) --------
__device__ __align__(16) int g_nbr[BATCH * NS * KNBR];

// -------- JAX threefry2x32 (20 rounds), host-usable --------
__host__ __device__ __forceinline__ void threefry2x32(
    uint32_t k0, uint32_t k1, uint32_t x0, uint32_t x1,
    uint32_t* o0, uint32_t* o1)
{
    uint32_t ks2 = k0 ^ k1 ^ 0x1BD11BDAu;
    x0 += k0; x1 += k1;
#define TF_ROT(x, r) (((x) << (r)) | ((x) >> (32 - (r))))
#define TF_R4(a, b, c, d)                       \
    x0 += x1; x1 = TF_ROT(x1, a); x1 ^= x0;     \
    x0 += x1; x1 = TF_ROT(x1, b); x1 ^= x0;     \
    x0 += x1; x1 = TF_ROT(x1, c); x1 ^= x0;     \
    x0 += x1; x1 = TF_ROT(x1, d); x1 ^= x0;
    TF_R4(13, 15, 26, 6);  x0 += k1;  x1 += ks2 + 1u;
    TF_R4(17, 29, 16, 24); x0 += ks2; x1 += k0 + 2u;
    TF_R4(13, 15, 26, 6);  x0 += k0;  x1 += k1 + 3u;
    TF_R4(17, 29, 16, 24); x0 += k1;  x1 += ks2 + 4u;
    TF_R4(13, 15, 26, 6);  x0 += ks2; x1 += k0 + 5u;
#undef TF_R4
#undef TF_ROT
    *o0 = x0; *o1 = x1;
}

// -------- mbarrier / TMA-bulk helpers --------
__device__ __forceinline__ void mbar_init(void* mbar, unsigned count)
{
    unsigned a = (unsigned)__cvta_generic_to_shared(mbar);
    asm volatile("mbarrier.init.shared.b64 [%0], %1;" :: "r"(a), "r"(count) : "memory");
}
__device__ __forceinline__ void mbar_expect_tx(void* mbar, unsigned bytes)
{
    unsigned a = (unsigned)__cvta_generic_to_shared(mbar);
    asm volatile("mbarrier.arrive.expect_tx.shared.b64 _, [%0], %1;"
                 :: "r"(a), "r"(bytes) : "memory");
}
__device__ __forceinline__ void bulk_g2s(void* dst, const void* src,
                                         unsigned bytes, void* mbar)
{
    unsigned d = (unsigned)__cvta_generic_to_shared(dst);
    unsigned m = (unsigned)__cvta_generic_to_shared(mbar);
    asm volatile(
        "cp.async.bulk.shared::cta.global.mbarrier::complete_tx::bytes "
        "[%0], [%1], %2, [%3];"
        :: "r"(d), "l"(src), "r"(bytes), "r"(m) : "memory");
}
__device__ __forceinline__ void mbar_wait(void* mbar, unsigned parity)
{
    unsigned a = (unsigned)__cvta_generic_to_shared(mbar);
    asm volatile(
        "{\n\t.reg .pred P;\n\t"
        "W%=:\n\t"
        "mbarrier.try_wait.parity.acquire.cta.shared::cta.b64 P, [%0], %1, 0x989680;\n\t"
        "@P bra.uni D%=;\n\t"
        "bra.uni W%=;\n\t"
        "D%=:\n\t}"
        :: "r"(a), "r"(parity) : "memory");
}

// ======================= K_knn ==============================================
// 8 queries per block; each warp scans a QUARTER (1024 points) for ALL 8
// queries. Phase 1: per-lane top-1 (fminf) -> 5-pop warp merge -> per-quarter
// threshold; t = min(quarters) >= d_(5). Phase 2: compact d<=t hits, exact
// rank by packed (monotone dist bits, idx). Self = rank 0, dropped.
// block = 128 (4 warps); grid = 4 * 128 = 512 blocks.
__global__ __launch_bounds__(128) void knn_kernel(const float* __restrict__ Vtx,
                                                  float* __restrict__ out,
                                                  Samp smp)
{
    extern __shared__ __align__(16) float sv[];      // [NV*3] packed xyz
    ull*   buf = (ull*)(sv + NV * 3);                // [8][CAND]
    int*   cnt = (int*)(buf + 8 * CAND);             // [8]
    float* tqs = (float*)(cnt + 8);                  // [8][4]
    __shared__ __align__(8) ull mbar;

    int b = blockIdx.x >> 7;
    int qg = blockIdx.x & 127;

    if (threadIdx.x == 0) mbar_init(&mbar, 1);
    if (threadIdx.x < 8) cnt[threadIdx.x] = 0;
    __syncthreads();
    if (threadIdx.x == 0) {
        mbar_expect_tx(&mbar, VBB);
        bulk_g2s(sv, Vtx + (size_t)b * NV * 3, VBB, &mbar);
    }
    mbar_wait(&mbar, 0);

    // first q-group block per batch also emits vertices_pool (b,1024,3)
    if (qg == 0) {
        for (int t = threadIdx.x; t < NS * 3; t += 128) {
            int s = t / 3, d = t - 3 * s;
            out[(b * NS + s) * 3 + d] = sv[smp.s[s] * 3 + d];
        }
    }

    int warp = threadIdx.x >> 5;
    int lane = threadIdx.x & 31;
    int sbase = qg * 8;

    float qx[8], qy[8], qz[8], qq[8];
#pragma unroll
    for (int qi = 0; qi < 8; ++qi) {
        int n = smp.s[sbase + qi];
        qx[qi] = sv[n * 3]; qy[qi] = sv[n * 3 + 1]; qz[qi] = sv[n * 3 + 2];
        qq[qi] = qx[qi] * qx[qi] + qy[qi] * qy[qi] + qz[qi] * qz[qi];
    }

    const float INF = __int_as_float(0x7f800000);
    float a[8] = {INF, INF, INF, INF, INF, INF, INF, INF};
    int mbeg = warp * 1024 + lane, mend = warp * 1024 + 1024;

    // ---- Phase 1: per-lane running min per query over this quarter ----
    for (int m = mbeg; m < mend; m += 32) {
        float xm = sv[m * 3], ym = sv[m * 3 + 1], zm = sv[m * 3 + 2];
        float qm = xm * xm + ym * ym + zm * zm;
#pragma unroll
        for (int qi = 0; qi < 8; ++qi) {
            float inner = qx[qi] * xm + qy[qi] * ym + qz[qi] * zm;
            float d = (-2.0f * inner + qm) + qq[qi];   // matches reference assoc
            a[qi] = fminf(a[qi], d);
        }
    }

    // ---- per-quarter 5-pop merge -> threshold; min over quarters in smem ---
#pragma unroll
    for (int qi = 0; qi < 8; ++qi) {
        float h = a[qi], t = INF;
#pragma unroll
        for (int p = 0; p < 5; ++p) {
            float mn = h;
#pragma unroll
            for (int off = 16; off; off >>= 1)
                mn = fminf(mn, __shfl_xor_sync(0xffffffffu, mn, off));
            h = (h == mn) ? INF : h;
            t = mn;
        }
        if (lane == 0) tqs[qi * 4 + warp] = t;
    }
    __syncthreads();

    float tq[8];
#pragma unroll
    for (int qi = 0; qi < 8; ++qi)
        tq[qi] = fminf(fminf(tqs[qi * 4], tqs[qi * 4 + 1]),
                       fminf(tqs[qi * 4 + 2], tqs[qi * 4 + 3]));

    // ---- Phase 2: collect all m with d <= t (shared counters per query) ----
    for (int m = mbeg; m < mend; m += 32) {
        float xm = sv[m * 3], ym = sv[m * 3 + 1], zm = sv[m * 3 + 2];
        float qm = xm * xm + ym * ym + zm * zm;
#pragma unroll
        for (int qi = 0; qi < 8; ++qi) {
            float inner = qx[qi] * xm + qy[qi] * ym + qz[qi] * zm;
            float d = (-2.0f * inner + qm) + qq[qi];
            if (d <= tq[qi]) {
                unsigned kb = __float_as_uint(d);
                kb ^= (kb & 0x80000000u) ? 0xffffffffu : 0x80000000u; // monotone
                int pos = atomicAdd(&cnt[qi], 1);
                if (pos < CAND) buf[qi * CAND + pos] = ((ull)kb << 32) | (unsigned)m;
            }
        }
    }
    __syncthreads();

    // ---- exact rank among candidates; warp w ranks queries 2w, 2w+1 ----
#pragma unroll
    for (int k = 0; k < 2; ++k) {
        int q = warp * 2 + k;
        int n = cnt[q]; if (n > CAND) n = CAND;
        const ull* bq = &buf[q * CAND];
        ull va = (lane < n) ? bq[lane] : ~0ULL;
        ull vb = (lane + 32 < n) ? bq[lane + 32] : ~0ULL;
        int ra = 0, rb = 0;
        for (int j = 0; j < n; ++j) {
            ull o = bq[j];               // broadcast LDS
            ra += (o < va); rb += (o < vb);
        }
        int base = (b * NS + (sbase + q)) * KNBR;
        if (lane < n && ra >= 1 && ra <= KNBR)
            g_nbr[base + ra - 1] = (int)(unsigned)(va & 0xffffffffULL);
        if (lane + 32 < n && rb >= 1 && rb <= KNBR)
            g_nbr[base + rb - 1] = (int)(unsigned)(vb & 0xffffffffULL);
    }
}

// ======================= K_pool =============================================
// Two planes per block, double-buffered TMA bulk; neighbor indices (shared by
// both planes — same batch) prefetched before the waits.
// grid = 256, block = 512, dynamic smem = 96KB -> 2 blocks/SM.
__global__ __launch_bounds__(512) void pool_kernel(const float* __restrict__ F,
                                                   float* __restrict__ out)
{
    extern __shared__ __align__(16) float sf[];   // [2 * PLF]
    __shared__ __align__(8) ull mbar[2];

    int pl0 = blockIdx.x * 2;            // planes pl0, pl0+1 (same batch)
    int b = pl0 >> 7;
    const int4* nbr4 = (const int4*)g_nbr + b * NS;

    // prefetch neighbor indices (independent of smem contents)
    int t0 = threadIdx.x, t1 = threadIdx.x + 512;
    int4 nbA = __ldg(&nbr4[t0]);
    int4 nbB = __ldg(&nbr4[t1]);

    if (threadIdx.x == 0) { mbar_init(&mbar[0], 1); mbar_init(&mbar[1], 1); }
    __syncthreads();
    if (threadIdx.x == 0) {
        mbar_expect_tx(&mbar[0], PLB);
        bulk_g2s(sf,       F + (size_t)pl0 * PLF,       PLB, &mbar[0]);
        mbar_expect_tx(&mbar[1], PLB);
        bulk_g2s(sf + PLF, F + (size_t)(pl0 + 1) * PLF, PLB, &mbar[1]);
    }

    int j0A = nbA.x * 3, j1A = nbA.y * 3, j2A = nbA.z * 3, j3A = nbA.w * 3;
    int j0B = nbB.x * 3, j1B = nbB.y * 3, j2B = nbB.z * 3, j3B = nbB.w * 3;

#pragma unroll
    for (int p = 0; p < 2; ++p) {
        mbar_wait(&mbar[p], 0);
        const float* sp = sf + p * PLF;
        float* fout = out + BATCH * NS * 3 + (size_t)(pl0 + p) * NS * 3;
        {
            float o0 = fmaxf(fmaxf(sp[j0A],     sp[j1A]),     fmaxf(sp[j2A],     sp[j3A]));
            float o1 = fmaxf(fmaxf(sp[j0A + 1], sp[j1A + 1]), fmaxf(sp[j2A + 1], sp[j3A + 1]));
            float o2 = fmaxf(fmaxf(sp[j0A + 2], sp[j1A + 2]), fmaxf(sp[j2A + 2], sp[j3A + 2]));
            fout[t0 * 3]     = o0;
            fout[t0 * 3 + 1] = o1;
            fout[t0 * 3 + 2] = o2;
        }
        {
            float o0 = fmaxf(fmaxf(sp[j0B],     sp[j1B]),     fmaxf(sp[j2B],     sp[j3B]));
            float o1 = fmaxf(fmaxf(sp[j0B + 1], sp[j1B + 1]), fmaxf(sp[j2B + 1], sp[j3B + 1]));
            float o2 = fmaxf(fmaxf(sp[j0B + 2], sp[j1B + 2]), fmaxf(sp[j2B + 2], sp[j3B + 2]));
            fout[t1 * 3]     = o0;
            fout[t1 * 3 + 1] = o1;
            fout[t1 * 3 + 2] = o2;
        }
    }
}

// ======================= host entry =========================================
extern "C" void kernel_launch(void* const* d_in, const int* in_sizes, int n_in,
                              void* d_out, int out_size)
{
    const float* Vtx;
    const float* F;
    if (in_sizes[0] == BATCH * NV * 3) {
        Vtx = (const float*)d_in[0];
        F   = (const float*)d_in[1];
    } else {
        Vtx = (const float*)d_in[1];
        F   = (const float*)d_in[0];
    }

    // ---- host-side permutation (pure arithmetic; runs at capture time) ----
    uint32_t k10, k11, sub_lo[2], sub_hi[2];
    threefry2x32(0u, 42u, 0u, 0u, &k10, &k11);             // round-1 carry key
    threefry2x32(0u, 42u, 0u, 1u, &sub_lo[0], &sub_hi[0]); // round-1 subkey
    threefry2x32(k10, k11, 0u, 1u, &sub_lo[1], &sub_hi[1]);// round-2 subkey

    static ull pk[NV];
    static int rk[2][NV];
    for (int r = 0; r < 2; ++r) {
        for (int i = 0; i < NV; ++i) {
            uint32_t w0, w1;
            threefry2x32(sub_lo[r], sub_hi[r], 0u, (uint32_t)i, &w0, &w1);
            pk[i] = ((ull)(w0 ^ w1) << 32) | (uint32_t)i;
        }
        std::sort(pk, pk + NV);   // index in low bits -> stable rank
        for (int j = 0; j < NV; ++j) rk[r][(uint32_t)pk[j]] = j;
    }
    static Samp h_samp;
    for (int i = 0; i < NV; ++i) {
        int pos = rk[1][rk[0][i]];
        if (pos < NS) h_samp.s[pos] = i;
    }

    int knn_smem = NV * 3 * (int)sizeof(float) + 8 * CAND * (int)sizeof(ull)
                 + 8 * (int)sizeof(int) + 32 * (int)sizeof(float);
    int pool_smem = 2 * PLB;
    cudaFuncSetAttribute(knn_kernel,
                         cudaFuncAttributeMaxDynamicSharedMemorySize, knn_smem);
    cudaFuncSetAttribute(pool_kernel,
                         cudaFuncAttributeMaxDynamicSharedMemorySize, pool_smem);

    knn_kernel<<<512, 128, knn_smem>>>(Vtx, (float*)d_out, h_samp);
    pool_kernel<<<256, 512, pool_smem>>>(F, (float*)d_out);
}

// round 9
// speedup vs baseline: 1.0434x; 1.0434x over previous
#include <cuda_runtime.h>
#include <cstdint>
#include <algorithm>

// Problem constants (fixed by dataset shapes)
#define BATCH 4
#define NV    4096
#define NC    128
#define NS    1024   // NV / POOLING_RATE
#define KNBR  4
#define PLF   (NV * 3)        // floats per (b,c) feature plane = 12288
#define PLB   (PLF * 4)       // bytes per plane = 49152
#define CAND  96              // phase-2 candidate buffer depth per query

typedef unsigned long long ull;

struct Samp { int s[NS]; };   // 4KB by-value kernel parameter

// -------- device scratch (no allocation allowed) --------
__device__ __align__(16) int g_nbr[BATCH * NS * KNBR];

// -------- JAX threefry2x32 (20 rounds), host-usable --------
__host__ __device__ __forceinline__ void threefry2x32(
    uint32_t k0, uint32_t k1, uint32_t x0, uint32_t x1,
    uint32_t* o0, uint32_t* o1)
{
    uint32_t ks2 = k0 ^ k1 ^ 0x1BD11BDAu;
    x0 += k0; x1 += k1;
#define TF_ROT(x, r) (((x) << (r)) | ((x) >> (32 - (r))))
#define TF_R4(a, b, c, d)                       \
    x0 += x1; x1 = TF_ROT(x1, a); x1 ^= x0;     \
    x0 += x1; x1 = TF_ROT(x1, b); x1 ^= x0;     \
    x0 += x1; x1 = TF_ROT(x1, c); x1 ^= x0;     \
    x0 += x1; x1 = TF_ROT(x1, d); x1 ^= x0;
    TF_R4(13, 15, 26, 6);  x0 += k1;  x1 += ks2 + 1u;
    TF_R4(17, 29, 16, 24); x0 += ks2; x1 += k0 + 2u;
    TF_R4(13, 15, 26, 6);  x0 += k0;  x1 += k1 + 3u;
    TF_R4(17, 29, 16, 24); x0 += k1;  x1 += ks2 + 4u;
    TF_R4(13, 15, 26, 6);  x0 += ks2; x1 += k0 + 5u;
#undef TF_R4
#undef TF_ROT
    *o0 = x0; *o1 = x1;
}

// -------- mbarrier / TMA-bulk helpers --------
__device__ __forceinline__ void mbar_init(void* mbar, unsigned count)
{
    unsigned a = (unsigned)__cvta_generic_to_shared(mbar);
    asm volatile("mbarrier.init.shared.b64 [%0], %1;" :: "r"(a), "r"(count) : "memory");
}
__device__ __forceinline__ void mbar_expect_tx(void* mbar, unsigned bytes)
{
    unsigned a = (unsigned)__cvta_generic_to_shared(mbar);
    asm volatile("mbarrier.arrive.expect_tx.shared.b64 _, [%0], %1;"
                 :: "r"(a), "r"(bytes) : "memory");
}
__device__ __forceinline__ void bulk_g2s(void* dst, const void* src,
                                         unsigned bytes, void* mbar)
{
    unsigned d = (unsigned)__cvta_generic_to_shared(dst);
    unsigned m = (unsigned)__cvta_generic_to_shared(mbar);
    asm volatile(
        "cp.async.bulk.shared::cta.global.mbarrier::complete_tx::bytes "
        "[%0], [%1], %2, [%3];"
        :: "r"(d), "l"(src), "r"(bytes), "r"(m) : "memory");
}
__device__ __forceinline__ void mbar_wait(void* mbar, unsigned parity)
{
    unsigned a = (unsigned)__cvta_generic_to_shared(mbar);
    asm volatile(
        "{\n\t.reg .pred P;\n\t"
        "W%=:\n\t"
        "mbarrier.try_wait.parity.acquire.cta.shared::cta.b64 P, [%0], %1, 0x989680;\n\t"
        "@P bra.uni D%=;\n\t"
        "bra.uni W%=;\n\t"
        "D%=:\n\t}"
        :: "r"(a), "r"(parity) : "memory");
}

// -------- packed f32x2 helpers (sm_100a) --------
__device__ __forceinline__ ull lds_b64(const float* p)
{
    ull r; unsigned a = (unsigned)__cvta_generic_to_shared(p);
    asm volatile("ld.shared.b64 %0, [%1];" : "=l"(r) : "r"(a));
    return r;
}
__device__ __forceinline__ ull pack2(float v)
{
    ull r; asm("mov.b64 %0, {%1, %1};" : "=l"(r) : "f"(v)); return r;
}
__device__ __forceinline__ ull mul2(ull a, ull b)
{
    ull r; asm("mul.rn.f32x2 %0, %1, %2;" : "=l"(r) : "l"(a), "l"(b)); return r;
}
__device__ __forceinline__ ull fma2(ull a, ull b, ull c)
{
    ull r; asm("fma.rn.f32x2 %0, %1, %2, %3;" : "=l"(r) : "l"(a), "l"(b), "l"(c));
    return r;
}
__device__ __forceinline__ void unpack2(ull v, float& lo, float& hi)
{
    asm("mov.b64 {%0, %1}, %2;" : "=f"(lo), "=f"(hi) : "l"(v));
}

// ======================= K_knn ==============================================
// 8 queries per block; each warp scans a QUARTER (1024 points) for ALL 8
// queries, 2 points per lane per iter via f32x2 packed math on SoA smem.
// Metric: e = fma(-2, inner, qm)  (reference d minus the per-query constant
// qq — monotone-identical ordering). Phase 1: per-lane min -> 5-pop merge ->
// per-quarter threshold; t = min(quarters) >= e_(5). Phase 2: compact e<=t
// hits, exact rank by packed (monotone e bits, idx). Self = rank 0, dropped.
// block = 128 (4 warps); grid = 4 * 128 = 512 blocks.
__global__ __launch_bounds__(128) void knn_kernel(const float* __restrict__ Vtx,
                                                  float* __restrict__ out,
                                                  Samp smp)
{
    extern __shared__ __align__(16) float sx[];      // [NV] SoA
    float* sy = sx + NV;
    float* sz = sy + NV;
    ull*   buf = (ull*)(sz + NV);                    // [8][CAND]
    int*   cnt = (int*)(buf + 8 * CAND);             // [8]
    float* tqs = (float*)(cnt + 8);                  // [8][4]

    int b = blockIdx.x >> 7;
    int qg = blockIdx.x & 127;

    if (threadIdx.x < 8) cnt[threadIdx.x] = 0;

    // stage vertices SoA: 4 points (3 float4) per thread-iteration
    {
        const float4* vb4 = (const float4*)(Vtx + (size_t)b * NV * 3);
        for (int c = threadIdx.x; c < NV / 4; c += 128) {
            float4 a = vb4[3 * c], d4 = vb4[3 * c + 1], e4 = vb4[3 * c + 2];
            int p = 4 * c;
            sx[p]     = a.x;  sy[p]     = a.y;  sz[p]     = a.z;
            sx[p + 1] = a.w;  sy[p + 1] = d4.x; sz[p + 1] = d4.y;
            sx[p + 2] = d4.z; sy[p + 2] = d4.w; sz[p + 2] = e4.x;
            sx[p + 3] = e4.y; sy[p + 3] = e4.z; sz[p + 3] = e4.w;
        }
    }
    __syncthreads();

    // first q-group block per batch also emits vertices_pool (b,1024,3)
    if (qg == 0) {
        for (int t = threadIdx.x; t < NS * 3; t += 128) {
            int s = t / 3, d = t - 3 * s;
            float v = (d == 0) ? sx[smp.s[s]] : (d == 1) ? sy[smp.s[s]] : sz[smp.s[s]];
            out[(b * NS + s) * 3 + d] = v;
        }
    }

    int warp = threadIdx.x >> 5;
    int lane = threadIdx.x & 31;
    int sbase = qg * 8;

    ull qx2[8], qy2[8], qz2[8];
#pragma unroll
    for (int qi = 0; qi < 8; ++qi) {
        int n = smp.s[sbase + qi];
        qx2[qi] = pack2(sx[n]); qy2[qi] = pack2(sy[n]); qz2[qi] = pack2(sz[n]);
    }
    const ull NEG2 = pack2(-2.0f);

    const float INF = __int_as_float(0x7f800000);
    float amlo[8], amhi[8];
#pragma unroll
    for (int qi = 0; qi < 8; ++qi) { amlo[qi] = INF; amhi[qi] = INF; }

    int pbeg = warp * 1024 + lane * 2;   // lane owns point pair (p, p+1), step 64

    // ---- Phase 1: per-lane running min of e per query (2 points packed) ----
    {
        int p = pbeg;
#pragma unroll 2
        for (int it = 0; it < 16; ++it, p += 64) {
            ull x2 = lds_b64(sx + p), y2 = lds_b64(sy + p), z2 = lds_b64(sz + p);
            ull qm2 = mul2(x2, x2);
            qm2 = fma2(y2, y2, qm2);
            qm2 = fma2(z2, z2, qm2);
#pragma unroll
            for (int qi = 0; qi < 8; ++qi) {
                ull in2 = mul2(qx2[qi], x2);
                in2 = fma2(qy2[qi], y2, in2);
                in2 = fma2(qz2[qi], z2, in2);
                ull e2 = fma2(NEG2, in2, qm2);
                float el, eh; unpack2(e2, el, eh);
                amlo[qi] = fminf(amlo[qi], el);
                amhi[qi] = fminf(amhi[qi], eh);
            }
        }
    }

    // ---- per-quarter 5-pop merge -> threshold; min over quarters in smem ---
#pragma unroll
    for (int qi = 0; qi < 8; ++qi) {
        float h = fminf(amlo[qi], amhi[qi]), t = INF;
#pragma unroll
        for (int p = 0; p < 5; ++p) {
            float mn = h;
#pragma unroll
            for (int off = 16; off; off >>= 1)
                mn = fminf(mn, __shfl_xor_sync(0xffffffffu, mn, off));
            h = (h == mn) ? INF : h;
            t = mn;
        }
        if (lane == 0) tqs[qi * 4 + warp] = t;
    }
    __syncthreads();

    float tq[8];
#pragma unroll
    for (int qi = 0; qi < 8; ++qi)
        tq[qi] = fminf(fminf(tqs[qi * 4], tqs[qi * 4 + 1]),
                       fminf(tqs[qi * 4 + 2], tqs[qi * 4 + 3]));

    // NOTE per-lane min is an upper bound on this lane's min; the 5-pop over
    // lane minima is >= e_(5) of the quarter >= e_(5) global (subset order
    // statistics) -> phase 2 collects a superset of the exact top-5.

    // ---- Phase 2: collect all points with e <= t ----
    {
        int p = pbeg;
        for (int it = 0; it < 16; ++it, p += 64) {
            ull x2 = lds_b64(sx + p), y2 = lds_b64(sy + p), z2 = lds_b64(sz + p);
            ull qm2 = mul2(x2, x2);
            qm2 = fma2(y2, y2, qm2);
            qm2 = fma2(z2, z2, qm2);
#pragma unroll
            for (int qi = 0; qi < 8; ++qi) {
                ull in2 = mul2(qx2[qi], x2);
                in2 = fma2(qy2[qi], y2, in2);
                in2 = fma2(qz2[qi], z2, in2);
                ull e2 = fma2(NEG2, in2, qm2);
                float el, eh; unpack2(e2, el, eh);
                if (el <= tq[qi]) {
                    unsigned kb = __float_as_uint(el);
                    kb ^= (kb & 0x80000000u) ? 0xffffffffu : 0x80000000u;
                    int pos = atomicAdd(&cnt[qi], 1);
                    if (pos < CAND)
                        buf[qi * CAND + pos] = ((ull)kb << 32) | (unsigned)p;
                }
                if (eh <= tq[qi]) {
                    unsigned kb = __float_as_uint(eh);
                    kb ^= (kb & 0x80000000u) ? 0xffffffffu : 0x80000000u;
                    int pos = atomicAdd(&cnt[qi], 1);
                    if (pos < CAND)
                        buf[qi * CAND + pos] = ((ull)kb << 32) | (unsigned)(p + 1);
                }
            }
        }
    }
    __syncthreads();

    // ---- exact rank among candidates; warp w ranks queries 2w, 2w+1 ----
#pragma unroll
    for (int k = 0; k < 2; ++k) {
        int q = warp * 2 + k;
        int n = cnt[q]; if (n > CAND) n = CAND;
        const ull* bq = &buf[q * CAND];
        // each lane ranks up to 3 candidates (CAND = 96 = 3 * 32)
        ull v0 = (lane < n) ? bq[lane] : ~0ULL;
        ull v1 = (lane + 32 < n) ? bq[lane + 32] : ~0ULL;
        ull v2 = (lane + 64 < n) ? bq[lane + 64] : ~0ULL;
        int r0 = 0, r1 = 0, r2 = 0;
        for (int j = 0; j < n; ++j) {
            ull o = bq[j];               // broadcast LDS
            r0 += (o < v0); r1 += (o < v1); r2 += (o < v2);
        }
        int base = (b * NS + (sbase + q)) * KNBR;
        if (lane < n && r0 >= 1 && r0 <= KNBR)
            g_nbr[base + r0 - 1] = (int)(unsigned)(v0 & 0xffffffffULL);
        if (lane + 32 < n && r1 >= 1 && r1 <= KNBR)
            g_nbr[base + r1 - 1] = (int)(unsigned)(v1 & 0xffffffffULL);
        if (lane + 64 < n && r2 >= 1 && r2 <= KNBR)
            g_nbr[base + r2 - 1] = (int)(unsigned)(v2 & 0xffffffffULL);
    }
}

// ======================= K_pool =============================================
// One plane per block, TMA bulk stage, neighbor indices prefetched before the
// TMA wait. grid = 512, block = 512, dynamic smem = 48KB -> 4 blocks/SM.
// (Best-measured pool config: R7, 10.59us.)
__global__ __launch_bounds__(512) void pool_kernel(const float* __restrict__ F,
                                                   float* __restrict__ out)
{
    extern __shared__ __align__(16) float sf[];   // [PLF]
    __shared__ __align__(8) ull mbar;

    int pl = blockIdx.x;
    int b = pl >> 7;
    const int4* nbr4 = (const int4*)g_nbr + b * NS;

    // prefetch neighbor indices (independent of smem contents)
    int t0 = threadIdx.x, t1 = threadIdx.x + 512;
    int4 nbA = __ldg(&nbr4[t0]);
    int4 nbB = __ldg(&nbr4[t1]);

    if (threadIdx.x == 0) mbar_init(&mbar, 1);
    __syncthreads();
    if (threadIdx.x == 0) {
        mbar_expect_tx(&mbar, PLB);
        bulk_g2s(sf, F + (size_t)pl * PLF, PLB, &mbar);
    }
    mbar_wait(&mbar, 0);

    float* fout = out + BATCH * NS * 3 + (size_t)pl * NS * 3;
    {
        int j0 = nbA.x * 3, j1 = nbA.y * 3, j2 = nbA.z * 3, j3 = nbA.w * 3;
        float o0 = fmaxf(fmaxf(sf[j0],     sf[j1]),     fmaxf(sf[j2],     sf[j3]));
        float o1 = fmaxf(fmaxf(sf[j0 + 1], sf[j1 + 1]), fmaxf(sf[j2 + 1], sf[j3 + 1]));
        float o2 = fmaxf(fmaxf(sf[j0 + 2], sf[j1 + 2]), fmaxf(sf[j2 + 2], sf[j3 + 2]));
        fout[t0 * 3]     = o0;
        fout[t0 * 3 + 1] = o1;
        fout[t0 * 3 + 2] = o2;
    }
    {
        int j0 = nbB.x * 3, j1 = nbB.y * 3, j2 = nbB.z * 3, j3 = nbB.w * 3;
        float o0 = fmaxf(fmaxf(sf[j0],     sf[j1]),     fmaxf(sf[j2],     sf[j3]));
        float o1 = fmaxf(fmaxf(sf[j0 + 1], sf[j1 + 1]), fmaxf(sf[j2 + 1], sf[j3 + 1]));
        float o2 = fmaxf(fmaxf(sf[j0 + 2], sf[j1 + 2]), fmaxf(sf[j2 + 2], sf[j3 + 2]));
        fout[t1 * 3]     = o0;
        fout[t1 * 3 + 1] = o1;
        fout[t1 * 3 + 2] = o2;
    }
}

// ======================= host entry =========================================
extern "C" void kernel_launch(void* const* d_in, const int* in_sizes, int n_in,
                              void* d_out, int out_size)
{
    const float* Vtx;
    const float* F;
    if (in_sizes[0] == BATCH * NV * 3) {
        Vtx = (const float*)d_in[0];
        F   = (const float*)d_in[1];
    } else {
        Vtx = (const float*)d_in[1];
        F   = (const float*)d_in[0];
    }

    // ---- host-side permutation (pure arithmetic; runs at capture time) ----
    uint32_t k10, k11, sub_lo[2], sub_hi[2];
    threefry2x32(0u, 42u, 0u, 0u, &k10, &k11);             // round-1 carry key
    threefry2x32(0u, 42u, 0u, 1u, &sub_lo[0], &sub_hi[0]); // round-1 subkey
    threefry2x32(k10, k11, 0u, 1u, &sub_lo[1], &sub_hi[1]);// round-2 subkey

    static ull pk[NV];
    static int rk[2][NV];
    for (int r = 0; r < 2; ++r) {
        for (int i = 0; i < NV; ++i) {
            uint32_t w0, w1;
            threefry2x32(sub_lo[r], sub_hi[r], 0u, (uint32_t)i, &w0, &w1);
            pk[i] = ((ull)(w0 ^ w1) << 32) | (uint32_t)i;
        }
        std::sort(pk, pk + NV);   // index in low bits -> stable rank
        for (int j = 0; j < NV; ++j) rk[r][(uint32_t)pk[j]] = j;
    }
    static Samp h_samp;
    for (int i = 0; i < NV; ++i) {
        int pos = rk[1][rk[0][i]];
        if (pos < NS) h_samp.s[pos] = i;
    }

    int knn_smem = NV * 3 * (int)sizeof(float) + 8 * CAND * (int)sizeof(ull)
                 + 8 * (int)sizeof(int) + 32 * (int)sizeof(float);
    int pool_smem = PLB;
    cudaFuncSetAttribute(knn_kernel,
                         cudaFuncAttributeMaxDynamicSharedMemorySize, knn_smem);
    cudaFuncSetAttribute(pool_kernel,
                         cudaFuncAttributeMaxDynamicSharedMemorySize, pool_smem);

    knn_kernel<<<512, 128, knn_smem>>>(Vtx, (float*)d_out, h_samp);
    pool_kernel<<<512, 512, pool_smem>>>(F, (float*)d_out);
}

// round 10
// speedup vs baseline: 1.2035x; 1.1534x over previous
#include <cuda_runtime.h>
#include <cstdint>
#include <algorithm>

// Problem constants (fixed by dataset shapes)
#define BATCH 4
#define NV    4096
#define NC    128
#define NS    1024   // NV / POOLING_RATE
#define KNBR  4
#define PLF   (NV * 3)        // floats per (b,c) feature plane = 12288
#define PLB   (PLF * 4)       // bytes per plane = 49152

typedef unsigned long long ull;

struct Samp { int s[NS]; };   // 4KB by-value kernel parameter

// -------- device scratch (no allocation allowed) --------
__device__ __align__(16) int g_nbr[BATCH * NS * KNBR];

// -------- JAX threefry2x32 (20 rounds), host-usable --------
__host__ __device__ __forceinline__ void threefry2x32(
    uint32_t k0, uint32_t k1, uint32_t x0, uint32_t x1,
    uint32_t* o0, uint32_t* o1)
{
    uint32_t ks2 = k0 ^ k1 ^ 0x1BD11BDAu;
    x0 += k0; x1 += k1;
#define TF_ROT(x, r) (((x) << (r)) | ((x) >> (32 - (r))))
#define TF_R4(a, b, c, d)                       \
    x0 += x1; x1 = TF_ROT(x1, a); x1 ^= x0;     \
    x0 += x1; x1 = TF_ROT(x1, b); x1 ^= x0;     \
    x0 += x1; x1 = TF_ROT(x1, c); x1 ^= x0;     \
    x0 += x1; x1 = TF_ROT(x1, d); x1 ^= x0;
    TF_R4(13, 15, 26, 6);  x0 += k1;  x1 += ks2 + 1u;
    TF_R4(17, 29, 16, 24); x0 += ks2; x1 += k0 + 2u;
    TF_R4(13, 15, 26, 6);  x0 += k0;  x1 += k1 + 3u;
    TF_R4(17, 29, 16, 24); x0 += k1;  x1 += ks2 + 4u;
    TF_R4(13, 15, 26, 6);  x0 += ks2; x1 += k0 + 5u;
#undef TF_R4
#undef TF_ROT
    *o0 = x0; *o1 = x1;
}

// -------- mbarrier / TMA-bulk helpers (pool) --------
__device__ __forceinline__ void mbar_init(void* mbar, unsigned count)
{
    unsigned a = (unsigned)__cvta_generic_to_shared(mbar);
    asm volatile("mbarrier.init.shared.b64 [%0], %1;" :: "r"(a), "r"(count) : "memory");
}
__device__ __forceinline__ void mbar_expect_tx(void* mbar, unsigned bytes)
{
    unsigned a = (unsigned)__cvta_generic_to_shared(mbar);
    asm volatile("mbarrier.arrive.expect_tx.shared.b64 _, [%0], %1;"
                 :: "r"(a), "r"(bytes) : "memory");
}
__device__ __forceinline__ void bulk_g2s(void* dst, const void* src,
                                         unsigned bytes, void* mbar)
{
    unsigned d = (unsigned)__cvta_generic_to_shared(dst);
    unsigned m = (unsigned)__cvta_generic_to_shared(mbar);
    asm volatile(
        "cp.async.bulk.shared::cta.global.mbarrier::complete_tx::bytes "
        "[%0], [%1], %2, [%3];"
        :: "r"(d), "l"(src), "r"(bytes), "r"(m) : "memory");
}
__device__ __forceinline__ void mbar_wait(void* mbar, unsigned parity)
{
    unsigned a = (unsigned)__cvta_generic_to_shared(mbar);
    asm volatile(
        "{\n\t.reg .pred P;\n\t"
        "W%=:\n\t"
        "mbarrier.try_wait.parity.acquire.cta.shared::cta.b64 P, [%0], %1, 0x989680;\n\t"
        "@P bra.uni D%=;\n\t"
        "bra.uni W%=;\n\t"
        "D%=:\n\t}"
        :: "r"(a), "r"(parity) : "memory");
}

// ======================= K_knn ==============================================
// Single pass. 8 queries per block; warp w scans quarter w (1024 pts) for all
// 8 queries, 2 points per lane per iter (float2 SoA loads). Sort key = e with
// low 5 mantissa bits replaced by the lane-local point id (<=31 ulp perturb,
// id recoverable from bits). Per lane: branchless sorted top-3. Per quarter:
// pop-6 via warp-min butterflies -> 24 candidates/query -> exact fp32 rescore
// + (monotone e bits, idx) rank. Self = rank 0, dropped.
// block = 128 (4 warps); grid = 4 * 128 = 512 blocks.
__global__ __launch_bounds__(128) void knn_kernel(const float* __restrict__ Vtx,
                                                  float* __restrict__ out,
                                                  Samp smp)
{
    extern __shared__ __align__(16) float sx[];      // [NV] SoA
    float* sy = sx + NV;
    float* sz = sy + NV;
    int*   cand = (int*)(sz + NV);                   // [4][8][6] = 192 ints
    ull*   kbuf = (ull*)(cand + 192);                // [8][24]

    int b = blockIdx.x >> 7;
    int qg = blockIdx.x & 127;

    // stage vertices SoA: 4 points (3 float4) per thread-iteration
    {
        const float4* vb4 = (const float4*)(Vtx + (size_t)b * NV * 3);
        for (int c = threadIdx.x; c < NV / 4; c += 128) {
            float4 a = vb4[3 * c], d4 = vb4[3 * c + 1], e4 = vb4[3 * c + 2];
            int p = 4 * c;
            sx[p]     = a.x;  sy[p]     = a.y;  sz[p]     = a.z;
            sx[p + 1] = a.w;  sy[p + 1] = d4.x; sz[p + 1] = d4.y;
            sx[p + 2] = d4.z; sy[p + 2] = d4.w; sz[p + 2] = e4.x;
            sx[p + 3] = e4.y; sy[p + 3] = e4.z; sz[p + 3] = e4.w;
        }
    }
    __syncthreads();

    // first q-group block per batch also emits vertices_pool (b,1024,3)
    if (qg == 0) {
        for (int t = threadIdx.x; t < NS * 3; t += 128) {
            int s = t / 3, d = t - 3 * s;
            float v = (d == 0) ? sx[smp.s[s]] : (d == 1) ? sy[smp.s[s]] : sz[smp.s[s]];
            out[(b * NS + s) * 3 + d] = v;
        }
    }

    int warp = threadIdx.x >> 5;
    int lane = threadIdx.x & 31;
    int sbase = qg * 8;

    float qx[8], qy[8], qz[8];
#pragma unroll
    for (int qi = 0; qi < 8; ++qi) {
        int n = smp.s[sbase + qi];
        qx[qi] = sx[n]; qy[qi] = sy[n]; qz[qi] = sz[n];
    }

    const float INF = __int_as_float(0x7f800000);
    float k0[8], k1[8], k2[8];
#pragma unroll
    for (int qi = 0; qi < 8; ++qi) { k0[qi] = INF; k1[qi] = INF; k2[qi] = INF; }

    int base = warp * 1024 + lane * 2;   // lane owns (p, p+1), step 64

    // ---- main scan: e + key + sorted top-3 insert, per 2 points ----
#pragma unroll 4
    for (int it = 0; it < 16; ++it) {
        int p = base + it * 64;
        float2 x2 = *(const float2*)(sx + p);
        float2 y2 = *(const float2*)(sy + p);
        float2 z2 = *(const float2*)(sz + p);
        float qmA = fmaf(z2.x, z2.x, fmaf(y2.x, y2.x, x2.x * x2.x));
        float qmB = fmaf(z2.y, z2.y, fmaf(y2.y, y2.y, x2.y * x2.y));
        int locA = it * 2, locB = it * 2 + 1;
#pragma unroll
        for (int qi = 0; qi < 8; ++qi) {
            float eA = fmaf(-2.0f,
                fmaf(qz[qi], z2.x, fmaf(qy[qi], y2.x, qx[qi] * x2.x)), qmA);
            float fA = __int_as_float((__float_as_int(eA) & ~31) | locA);
            float t0 = fmaxf(k0[qi], fA); k0[qi] = fminf(k0[qi], fA);
            float t1 = fmaxf(k1[qi], t0); k1[qi] = fminf(k1[qi], t0);
            k2[qi] = fminf(k2[qi], t1);

            float eB = fmaf(-2.0f,
                fmaf(qz[qi], z2.y, fmaf(qy[qi], y2.y, qx[qi] * x2.y)), qmB);
            float fB = __int_as_float((__float_as_int(eB) & ~31) | locB);
            float u0 = fmaxf(k0[qi], fB); k0[qi] = fminf(k0[qi], fB);
            float u1 = fmaxf(k1[qi], u0); k1[qi] = fminf(k1[qi], u0);
            k2[qi] = fminf(k2[qi], u1);
        }
    }

    // ---- per-quarter pop-6 with index reconstruction ----
#pragma unroll
    for (int qi = 0; qi < 8; ++qi) {
        float a0 = k0[qi], a1 = k1[qi], a2 = k2[qi];
#pragma unroll
        for (int t = 0; t < 6; ++t) {
            float mn = a0;
#pragma unroll
            for (int off = 16; off; off >>= 1)
                mn = fminf(mn, __shfl_xor_sync(0xffffffffu, mn, off));
            unsigned bal = __ballot_sync(0xffffffffu, a0 == mn);
            int leader = __ffs(bal) - 1;
            if (lane == leader) {
                a0 = a1; a1 = a2; a2 = INF;
                int loc = __float_as_int(mn) & 31;
                int m = warp * 1024 + ((loc >> 1) << 6) + (leader << 1) + (loc & 1);
                cand[warp * 48 + qi * 6 + t] = m;
            }
        }
    }
    __syncthreads();

    // ---- exact rescore + rank of 24 candidates; warp w -> queries 2w,2w+1 --
#pragma unroll
    for (int kq = 0; kq < 2; ++kq) {
        int q = warp * 2 + kq;
        int nq = smp.s[sbase + q];
        float qxx = sx[nq], qyy = sy[nq], qzz = sz[nq];
        ull key = ~0ULL;
        int m = -1;
        if (lane < 24) {
            int quarter = lane / 6;
            int slot = lane - quarter * 6;
            m = cand[quarter * 48 + q * 6 + slot];
            float xm = sx[m], ym = sy[m], zm = sz[m];
            float qm = fmaf(zm, zm, fmaf(ym, ym, xm * xm));
            float e = fmaf(-2.0f, fmaf(qzz, zm, fmaf(qyy, ym, qxx * xm)), qm);
            unsigned kb = __float_as_uint(e);
            kb ^= (kb & 0x80000000u) ? 0xffffffffu : 0x80000000u; // monotone
            key = ((ull)kb << 32) | (unsigned)m;
            kbuf[q * 24 + lane] = key;
        }
        __syncwarp();
        int r = 0;
        for (int j = 0; j < 24; ++j) {
            ull o = kbuf[q * 24 + j];    // broadcast LDS
            r += (o < key);
        }
        if (lane < 24 && r >= 1 && r <= KNBR)
            g_nbr[(b * NS + (sbase + q)) * KNBR + (r - 1)] = m;
        __syncwarp();
    }
}

// ======================= K_pool =============================================
// One plane per block, TMA bulk stage, neighbor indices prefetched before the
// TMA wait. grid = 512, block = 512, dynamic smem = 48KB -> 4 blocks/SM.
__global__ __launch_bounds__(512) void pool_kernel(const float* __restrict__ F,
                                                   float* __restrict__ out)
{
    extern __shared__ __align__(16) float sf[];   // [PLF]
    __shared__ __align__(8) ull mbar;

    int pl = blockIdx.x;
    int b = pl >> 7;
    const int4* nbr4 = (const int4*)g_nbr + b * NS;

    int t0 = threadIdx.x, t1 = threadIdx.x + 512;
    int4 nbA = __ldg(&nbr4[t0]);
    int4 nbB = __ldg(&nbr4[t1]);

    if (threadIdx.x == 0) mbar_init(&mbar, 1);
    __syncthreads();
    if (threadIdx.x == 0) {
        mbar_expect_tx(&mbar, PLB);
        bulk_g2s(sf, F + (size_t)pl * PLF, PLB, &mbar);
    }
    mbar_wait(&mbar, 0);

    float* fout = out + BATCH * NS * 3 + (size_t)pl * NS * 3;
    {
        int j0 = nbA.x * 3, j1 = nbA.y * 3, j2 = nbA.z * 3, j3 = nbA.w * 3;
        float o0 = fmaxf(fmaxf(sf[j0],     sf[j1]),     fmaxf(sf[j2],     sf[j3]));
        float o1 = fmaxf(fmaxf(sf[j0 + 1], sf[j1 + 1]), fmaxf(sf[j2 + 1], sf[j3 + 1]));
        float o2 = fmaxf(fmaxf(sf[j0 + 2], sf[j1 + 2]), fmaxf(sf[j2 + 2], sf[j3 + 2]));
        fout[t0 * 3]     = o0;
        fout[t0 * 3 + 1] = o1;
        fout[t0 * 3 + 2] = o2;
    }
    {
        int j0 = nbB.x * 3, j1 = nbB.y * 3, j2 = nbB.z * 3, j3 = nbB.w * 3;
        float o0 = fmaxf(fmaxf(sf[j0],     sf[j1]),     fmaxf(sf[j2],     sf[j3]));
        float o1 = fmaxf(fmaxf(sf[j0 + 1], sf[j1 + 1]), fmaxf(sf[j2 + 1], sf[j3 + 1]));
        float o2 = fmaxf(fmaxf(sf[j0 + 2], sf[j1 + 2]), fmaxf(sf[j2 + 2], sf[j3 + 2]));
        fout[t1 * 3]     = o0;
        fout[t1 * 3 + 1] = o1;
        fout[t1 * 3 + 2] = o2;
    }
}

// ======================= host entry =========================================
extern "C" void kernel_launch(void* const* d_in, const int* in_sizes, int n_in,
                              void* d_out, int out_size)
{
    const float* Vtx;
    const float* F;
    if (in_sizes[0] == BATCH * NV * 3) {
        Vtx = (const float*)d_in[0];
        F   = (const float*)d_in[1];
    } else {
        Vtx = (const float*)d_in[1];
        F   = (const float*)d_in[0];
    }

    // ---- host-side permutation (pure arithmetic; runs at capture time) ----
    uint32_t k10, k11, sub_lo[2], sub_hi[2];
    threefry2x32(0u, 42u, 0u, 0u, &k10, &k11);             // round-1 carry key
    threefry2x32(0u, 42u, 0u, 1u, &sub_lo[0], &sub_hi[0]); // round-1 subkey
    threefry2x32(k10, k11, 0u, 1u, &sub_lo[1], &sub_hi[1]);// round-2 subkey

    static ull pk[NV];
    static int rk[2][NV];
    for (int r = 0; r < 2; ++r) {
        for (int i = 0; i < NV; ++i) {
            uint32_t w0, w1;
            threefry2x32(sub_lo[r], sub_hi[r], 0u, (uint32_t)i, &w0, &w1);
            pk[i] = ((ull)(w0 ^ w1) << 32) | (uint32_t)i;
        }
        std::sort(pk, pk + NV);   // index in low bits -> stable rank
        for (int j = 0; j < NV; ++j) rk[r][(uint32_t)pk[j]] = j;
    }
    static Samp h_samp;
    for (int i = 0; i < NV; ++i) {
        int pos = rk[1][rk[0][i]];
        if (pos < NS) h_samp.s[pos] = i;
    }

    int knn_smem = NV * 3 * (int)sizeof(float) + 192 * (int)sizeof(int)
                 + 8 * 24 * (int)sizeof(ull);
    int pool_smem = PLB;
    cudaFuncSetAttribute(knn_kernel,
                         cudaFuncAttributeMaxDynamicSharedMemorySize, knn_smem);
    cudaFuncSetAttribute(pool_kernel,
                         cudaFuncAttributeMaxDynamicSharedMemorySize, pool_smem);

    knn_kernel<<<512, 128, knn_smem>>>(Vtx, (float*)d_out, h_samp);
    pool_kernel<<<512, 512, pool_smem>>>(F, (float*)d_out);
}